// round 8
// baseline (speedup 1.0000x reference)
#include <cuda_runtime.h>
#include <math_constants.h>

// Problem constants
#define NUM_VARS 64
#define KK       32
#define NUM_CATS 256
#define NUM_INPUT (NUM_VARS * KK)   // 2048
#define LL       4
#define EE       16384
#define NN       8192
#define CC       4
#define BB       1024
#define Q4       (BB / 4)           // 256 ushort4-groups per row
#define TOTAL_NODES (NUM_INPUT + LL * NN)  // 34816
#define NCHUNK   64

#define GRID_BLOCKS 888             // 6 blocks/SM on 148 SMs — co-resident
#define THREADS     256
#define NTHREADS    (GRID_BLOCKS * THREADS)

#define LOG2E 1.4426950408889634f
#define LN2   0.6931471805599453f
#define QSCALE   128.0f             // u16 = -v_log2 * 128
#define INVQ     (1.0f / 128.0f)
#define LUT_N    2048               // corrections for d in [0, 16 log2)

// Node pool quantized to u16 (71.3 MB — fully L2-resident)
__device__ unsigned short g_node_q[(size_t)TOTAL_NODES * BB];
__device__ float g_partial[NCHUNK * BB];
__device__ uint2 g_pairs[LL * NN * CC];   // pre-scaled row offsets (row * Q4)
__device__ uint2 g_wq[LL * NN];           // 4 quantized weights packed u16x4

// Grid barrier
__device__ unsigned g_bar_count;
__device__ volatile unsigned g_bar_gen;

__device__ __forceinline__ void grid_sync() {
    __syncthreads();
    if (threadIdx.x == 0) {
        __threadfence();
        unsigned gen = g_bar_gen;
        if (atomicAdd(&g_bar_count, 1u) == GRID_BLOCKS - 1u) {
            g_bar_count = 0;
            __threadfence();
            g_bar_gen = gen + 1u;
        } else {
            while (g_bar_gen == gen) { }
        }
    }
    __syncthreads();
    __threadfence();
}

__device__ __forceinline__ float ex2(float x) {
    float r; asm("ex2.approx.ftz.f32 %0, %1;" : "=f"(r) : "f"(x)); return r;
}
__device__ __forceinline__ float lg2(float x) {
    float r; asm("lg2.approx.ftz.f32 %0, %1;" : "=f"(r) : "f"(x)); return r;
}

// integer logsumexp on u16x2 SIMD pairs (negated-log2 fixed point):
// lse2(qa,qb) = min(qa,qb) - lut[min(|qa-qb|, 2047)]
__device__ __forceinline__ unsigned lse2v(unsigned xa, unsigned xb,
                                          const unsigned* __restrict__ lut) {
    const unsigned mn = __vminu2(xa, xb);
    const unsigned d  = __vabsdiffu2(xa, xb);
    const unsigned clo = lut[umin(d & 0xFFFFu, LUT_N - 1u)];
    const unsigned chi = lut[umin(d >> 16,     LUT_N - 1u)];
    return __vsubus2(mn, __byte_perm(clo, chi, 0x5410));
}

__global__ void __launch_bounds__(THREADS, 6)
circuit_kernel(const int* __restrict__ inputs,
               const float* __restrict__ input_logp,
               const int2* __restrict__ prod_ids,     // (L, E)
               const int* __restrict__ sum_ch_ids,    // (L, N, C)
               const float4* __restrict__ sum_logw,   // (L, N) as float4
               const float* __restrict__ root_logw,   // (N,)
               float* __restrict__ out) {
    const int gtid = blockIdx.x * THREADS + threadIdx.x;

    // Per-block LSE-correction LUT: lut[d] = round(128*log2(1 + 2^(-d/128)))
    __shared__ unsigned s_lut[LUT_N];
    for (int i = threadIdx.x; i < LUT_N; i += THREADS)
        s_lut[i] = __float2uint_rn(QSCALE * lg2(1.0f + ex2(-(float)i * INVQ)));
    // (__syncthreads inside the first grid_sync covers LUT visibility)

    // ---------- Phase 0: input quantize + resolve + weight quantize ----------
    for (int idx = gtid; idx < NUM_INPUT * BB; idx += NTHREADS) {
        const int v = idx >> 15;
        const int k = (idx >> 10) & (KK - 1);
        const int b = idx & (BB - 1);
        const int cat = __ldg(inputs + b * NUM_VARS + v);
        const float lp2 = __ldg(input_logp + ((v * KK + k) << 8) + cat) * LOG2E;
        g_node_q[idx] = (unsigned short)umin(__float2uint_rn(-lp2 * QSCALE), 32767u);
    }
    for (int idx = gtid; idx < LL * NN * CC; idx += NTHREADS) {
        const int l = idx / (NN * CC);
        const int e = __ldg(sum_ch_ids + idx);
        const int2 p = __ldg(prod_ids + (size_t)l * EE + e);
        g_pairs[idx] = make_uint2((unsigned)p.x * Q4, (unsigned)p.y * Q4);
    }
    for (int idx = gtid; idx < LL * NN; idx += NTHREADS) {
        const float4 w = __ldg(sum_logw + idx);
        const unsigned q0 = umin(__float2uint_rn(-w.x * (LOG2E * QSCALE)), 65535u);
        const unsigned q1 = umin(__float2uint_rn(-w.y * (LOG2E * QSCALE)), 65535u);
        const unsigned q2 = umin(__float2uint_rn(-w.z * (LOG2E * QSCALE)), 65535u);
        const unsigned q3 = umin(__float2uint_rn(-w.w * (LOG2E * QSCALE)), 65535u);
        g_wq[idx] = make_uint2(q0 | (q1 << 16), q2 | (q3 << 16));
    }
    grid_sync();

    // ---------- Phases 1..4: sum layers — pure integer LSE --------------------
    const uint2* nq = reinterpret_cast<const uint2*>(g_node_q);
    uint2* nqo = reinterpret_cast<uint2*>(g_node_q);
    const unsigned c4 = threadIdx.x;   // ushort4-column 0..255

    for (int l = 0; l < LL; l++) {
        const int out_base = NUM_INPUT + l * NN;
        const uint4* prbase = reinterpret_cast<const uint4*>(g_pairs) + (size_t)l * NN * 2;
        const uint2* wqb = g_wq + (size_t)l * NN;

        for (int n = blockIdx.x; n < NN; n += GRID_BLOCKS) {
            const uint4 pa = __ldg(prbase + n * 2);
            const uint4 pb = __ldg(prbase + n * 2 + 1);
            const uint2 wp = __ldg(wqb + n);
            const unsigned wq0 = __byte_perm(wp.x, wp.x, 0x1010);  // u16x2 bcast
            const unsigned wq1 = __byte_perm(wp.x, wp.x, 0x3232);
            const unsigned wq2 = __byte_perm(wp.y, wp.y, 0x1010);
            const unsigned wq3 = __byte_perm(wp.y, wp.y, 0x3232);

            const uint2 a0 = __ldg(nq + pa.x + c4);
            const uint2 q0 = __ldg(nq + pa.y + c4);
            const uint2 a1 = __ldg(nq + pa.z + c4);
            const uint2 q1 = __ldg(nq + pa.w + c4);
            const uint2 a2 = __ldg(nq + pb.x + c4);
            const uint2 q2 = __ldg(nq + pb.y + c4);
            const uint2 a3 = __ldg(nq + pb.z + c4);
            const uint2 q3 = __ldg(nq + pb.w + c4);

            // child value = product pair-sum + weight (saturating u16x2)
            const unsigned x0x = __vaddus2(__vaddus2(a0.x, q0.x), wq0);
            const unsigned x1x = __vaddus2(__vaddus2(a1.x, q1.x), wq1);
            const unsigned x2x = __vaddus2(__vaddus2(a2.x, q2.x), wq2);
            const unsigned x3x = __vaddus2(__vaddus2(a3.x, q3.x), wq3);
            const unsigned x0y = __vaddus2(__vaddus2(a0.y, q0.y), wq0);
            const unsigned x1y = __vaddus2(__vaddus2(a1.y, q1.y), wq1);
            const unsigned x2y = __vaddus2(__vaddus2(a2.y, q2.y), wq2);
            const unsigned x3y = __vaddus2(__vaddus2(a3.y, q3.y), wq3);

            // lse4 = tree of integer lse2 — result is already stored format
            uint2 qo;
            qo.x = lse2v(lse2v(x0x, x1x, s_lut), lse2v(x2x, x3x, s_lut), s_lut);
            qo.y = lse2v(lse2v(x0y, x1y, s_lut), lse2v(x2y, x3y, s_lut), s_lut);
            nqo[(unsigned)(out_base + n) * Q4 + c4] = qo;
        }
        grid_sync();
    }

    // ---------- Phase 5: root partial logsumexp (decode u16, float) -----------
    {
        const unsigned short* last = g_node_q + (size_t)(NUM_INPUT + (LL - 1) * NN) * BB;
        const int idx = gtid;
        if (idx < NCHUNK * BB) {
            const int chunk = idx >> 10;
            const int b = idx & (BB - 1);
            const int n0 = chunk * (NN / NCHUNK);
            float m = -CUDART_INF_F, s = 0.f;
#pragma unroll 4
            for (int i = 0; i < NN / NCHUNK; i++) {
                const int n = n0 + i;
                const float nv = -(float)last[(unsigned)n * BB + b] * INVQ;
                const float x = fmaf(__ldg(root_logw + n), LOG2E, nv);
                const float mn = fmaxf(m, x);
                s = s * ex2(m - mn) + ex2(x - mn);
                m = mn;
            }
            g_partial[chunk * BB + b] = m + lg2(s);
        }
    }
    grid_sync();

    // ---------- Phase 6: final combine (-> natural log) -----------------------
    {
        const int wgid = gtid >> 5;
        const int lane = gtid & 31;
        if (wgid < BB) {
            const int b = wgid;
            const float x0 = g_partial[lane * BB + b];
            const float x1 = g_partial[(lane + 32) * BB + b];
            float m = fmaxf(x0, x1);
#pragma unroll
            for (int o = 16; o > 0; o >>= 1)
                m = fmaxf(m, __shfl_xor_sync(0xFFFFFFFF, m, o));
            float s = ex2(x0 - m) + ex2(x1 - m);
#pragma unroll
            for (int o = 16; o > 0; o >>= 1)
                s += __shfl_xor_sync(0xFFFFFFFF, s, o);
            if (lane == 0) out[b] = (m + lg2(s)) * LN2;
        }
    }
}

// ---------------------------------------------------------------------------
extern "C" void kernel_launch(void* const* d_in, const int* in_sizes, int n_in,
                              void* d_out, int out_size) {
    const int*   inputs     = (const int*)  d_in[0];
    const float* input_logp = (const float*)d_in[1];
    const int*   prod_ids   = (const int*)  d_in[2];  // (L, E, 2)
    const int*   sum_ch_ids = (const int*)  d_in[3];  // (L, N, C)
    const float* sum_logw   = (const float*)d_in[4];  // (L, N, C)
    const float* root_logw  = (const float*)d_in[5];  // (N,)
    float* out = (float*)d_out;

    circuit_kernel<<<GRID_BLOCKS, THREADS>>>(
        inputs, input_logp,
        reinterpret_cast<const int2*>(prod_ids),
        sum_ch_ids,
        reinterpret_cast<const float4*>(sum_logw),
        root_logw, out);
}

// round 9
// speedup vs baseline: 1.3247x; 1.3247x over previous
#include <cuda_runtime.h>
#include <math_constants.h>

// Problem constants
#define NUM_VARS 64
#define KK       32
#define NUM_CATS 256
#define NUM_INPUT (NUM_VARS * KK)   // 2048
#define LL       4
#define EE       16384
#define NN       8192
#define CC       4
#define BB       1024
#define Q4       (BB / 4)           // 256 ushort4-groups per row
#define TOTAL_NODES (NUM_INPUT + LL * NN)  // 34816
#define NCHUNK   64
#define WCHUNK   2                  // nodes per steal

#define GRID_BLOCKS 740             // 5 blocks/SM on 148 SMs — co-resident
#define THREADS     256
#define NTHREADS    (GRID_BLOCKS * THREADS)

#define LOG2E 1.4426950408889634f
#define LN2   0.6931471805599453f
#define QSCALE   128.0f             // u16 = -v_log2 * 128, clamp 32767
#define INVQ     (1.0f / 128.0f)
#define MAGIC    8388608.0f         // 2^23
#define MAGIC_HI 0x4B000000u

// Node pool quantized to u16 (71.3 MB — fully L2-resident)
__device__ unsigned short g_node_q[(size_t)TOTAL_NODES * BB];
__device__ float g_partial[NCHUNK * BB];
__device__ uint2 g_pairs[LL * NN * CC];   // pre-scaled row offsets (row * Q4)

// Grid barrier + per-layer work-steal counters
__device__ unsigned g_bar_count;
__device__ volatile unsigned g_bar_gen;
__device__ unsigned g_work[LL];

__device__ __forceinline__ void grid_sync() {
    __syncthreads();
    if (threadIdx.x == 0) {
        __threadfence();
        unsigned gen = g_bar_gen;
        if (atomicAdd(&g_bar_count, 1u) == GRID_BLOCKS - 1u) {
            g_bar_count = 0;
            __threadfence();
            g_bar_gen = gen + 1u;
        } else {
            while (g_bar_gen == gen) { }
        }
    }
    __syncthreads();
    __threadfence();
}

__device__ __forceinline__ float ex2(float x) {
    float r; asm("ex2.approx.ftz.f32 %0, %1;" : "=f"(r) : "f"(x)); return r;
}
__device__ __forceinline__ float lg2(float x) {
    float r; asm("lg2.approx.ftz.f32 %0, %1;" : "=f"(r) : "f"(x)); return r;
}

__device__ __forceinline__ float lse4_2(float a, float b, float c, float d) {
    float m = fmaxf(fmaxf(a, b), fmaxf(c, d));
    float s = ex2(a - m) + ex2(b - m) + ex2(c - m) + ex2(d - m);
    return m + lg2(s);
}

// PRMT decode: float bits = 0x4B00_(u16 half of s), then x = wq - f*INVQ
__device__ __forceinline__ float dec_lo(unsigned s, float wq) {
    const float f = __uint_as_float(__byte_perm(s, MAGIC_HI, 0x7610));
    return fmaf(f, -INVQ, wq);
}
__device__ __forceinline__ float dec_hi(unsigned s, float wq) {
    const float f = __uint_as_float(__byte_perm(s, MAGIC_HI, 0x7632));
    return fmaf(f, -INVQ, wq);
}

__device__ __forceinline__ unsigned enc1(float v_log2) {
    unsigned q = __float2uint_rn(-v_log2 * QSCALE);   // saturates at 0
    return umin(q, 32767u);
}

__global__ void __launch_bounds__(THREADS, 5)
circuit_kernel(const int* __restrict__ inputs,
               const float* __restrict__ input_logp,
               const int2* __restrict__ prod_ids,     // (L, E)
               const int* __restrict__ sum_ch_ids,    // (L, N, C)
               const float4* __restrict__ sum_logw,   // (L, N) as float4
               const float* __restrict__ root_logw,   // (N,)
               float* __restrict__ out) {
    const int gtid = blockIdx.x * THREADS + threadIdx.x;
    __shared__ unsigned s_base;

    // ---------- Phase 0: input quantize + resolve + counter reset -------------
    if (gtid < LL) g_work[gtid] = 0;
    for (int idx = gtid; idx < NUM_INPUT * BB; idx += NTHREADS) {
        const int v = idx >> 15;
        const int k = (idx >> 10) & (KK - 1);
        const int b = idx & (BB - 1);
        const int cat = __ldg(inputs + b * NUM_VARS + v);
        const float lp2 = __ldg(input_logp + ((v * KK + k) << 8) + cat) * LOG2E;
        g_node_q[idx] = (unsigned short)enc1(lp2);
    }
    for (int idx = gtid; idx < LL * NN * CC; idx += NTHREADS) {
        const int l = idx / (NN * CC);
        const int e = __ldg(sum_ch_ids + idx);
        const int2 p = __ldg(prod_ids + (size_t)l * EE + e);
        g_pairs[idx] = make_uint2((unsigned)p.x * Q4, (unsigned)p.y * Q4);
    }
    grid_sync();

    // ---------- Phases 1..4: sum layers (work-stealing over nodes) ------------
    const uint2* nq = reinterpret_cast<const uint2*>(g_node_q);
    uint2* nqo = reinterpret_cast<uint2*>(g_node_q);
    const unsigned c4 = threadIdx.x;   // ushort4-column 0..255

    for (int l = 0; l < LL; l++) {
        const int out_base = NUM_INPUT + l * NN;
        const uint4* prbase = reinterpret_cast<const uint4*>(g_pairs) + (size_t)l * NN * 2;
        const float4* lw = sum_logw + (size_t)l * NN;

        for (;;) {
            __syncthreads();
            if (threadIdx.x == 0) s_base = atomicAdd(&g_work[l], WCHUNK);
            __syncthreads();
            const unsigned base = s_base;
            if (base >= NN) break;

#pragma unroll
            for (int i = 0; i < WCHUNK; i++) {
                const unsigned n = base + i;
                const uint4 pa = __ldg(prbase + n * 2);
                const uint4 pb = __ldg(prbase + n * 2 + 1);
                const float4 w = __ldg(lw + n);
                const float wq0 = fmaf(w.x, LOG2E, MAGIC * INVQ);
                const float wq1 = fmaf(w.y, LOG2E, MAGIC * INVQ);
                const float wq2 = fmaf(w.z, LOG2E, MAGIC * INVQ);
                const float wq3 = fmaf(w.w, LOG2E, MAGIC * INVQ);

                const uint2 a0 = __ldg(nq + pa.x + c4);
                const uint2 q0 = __ldg(nq + pa.y + c4);
                const uint2 a1 = __ldg(nq + pa.z + c4);
                const uint2 q1 = __ldg(nq + pa.w + c4);
                const uint2 a2 = __ldg(nq + pb.x + c4);
                const uint2 q2 = __ldg(nq + pb.y + c4);
                const uint2 a3 = __ldg(nq + pb.z + c4);
                const uint2 q3 = __ldg(nq + pb.w + c4);

                const unsigned s0x = __vadd2(a0.x, q0.x), s0y = __vadd2(a0.y, q0.y);
                const unsigned s1x = __vadd2(a1.x, q1.x), s1y = __vadd2(a1.y, q1.y);
                const unsigned s2x = __vadd2(a2.x, q2.x), s2y = __vadd2(a2.y, q2.y);
                const unsigned s3x = __vadd2(a3.x, q3.x), s3y = __vadd2(a3.y, q3.y);

                const float o0 = lse4_2(dec_lo(s0x, wq0), dec_lo(s1x, wq1),
                                        dec_lo(s2x, wq2), dec_lo(s3x, wq3));
                const float o1 = lse4_2(dec_hi(s0x, wq0), dec_hi(s1x, wq1),
                                        dec_hi(s2x, wq2), dec_hi(s3x, wq3));
                const float o2 = lse4_2(dec_lo(s0y, wq0), dec_lo(s1y, wq1),
                                        dec_lo(s2y, wq2), dec_lo(s3y, wq3));
                const float o3 = lse4_2(dec_hi(s0y, wq0), dec_hi(s1y, wq1),
                                        dec_hi(s2y, wq2), dec_hi(s3y, wq3));

                uint2 qo;
                qo.x = __byte_perm(enc1(o0), enc1(o1), 0x5410);
                qo.y = __byte_perm(enc1(o2), enc1(o3), 0x5410);
                nqo[(unsigned)(out_base + n) * Q4 + c4] = qo;
            }
        }
        grid_sync();
    }

    // ---------- Phase 5: root partial logsumexp (decode u16, float) -----------
    {
        const unsigned short* last = g_node_q + (size_t)(NUM_INPUT + (LL - 1) * NN) * BB;
        const int idx = gtid;
        if (idx < NCHUNK * BB) {
            const int chunk = idx >> 10;
            const int b = idx & (BB - 1);
            const int n0 = chunk * (NN / NCHUNK);
            float m = -CUDART_INF_F, s = 0.f;
#pragma unroll 4
            for (int i = 0; i < NN / NCHUNK; i++) {
                const int n = n0 + i;
                const float nv = -(float)last[(unsigned)n * BB + b] * INVQ;
                const float x = fmaf(__ldg(root_logw + n), LOG2E, nv);
                const float mn = fmaxf(m, x);
                s = s * ex2(m - mn) + ex2(x - mn);
                m = mn;
            }
            g_partial[chunk * BB + b] = m + lg2(s);
        }
    }
    grid_sync();

    // ---------- Phase 6: final combine (-> natural log) -----------------------
    {
        const int wgid = gtid >> 5;
        const int lane = gtid & 31;
        if (wgid < BB) {
            const int b = wgid;
            const float x0 = g_partial[lane * BB + b];
            const float x1 = g_partial[(lane + 32) * BB + b];
            float m = fmaxf(x0, x1);
#pragma unroll
            for (int o = 16; o > 0; o >>= 1)
                m = fmaxf(m, __shfl_xor_sync(0xFFFFFFFF, m, o));
            float s = ex2(x0 - m) + ex2(x1 - m);
#pragma unroll
            for (int o = 16; o > 0; o >>= 1)
                s += __shfl_xor_sync(0xFFFFFFFF, s, o);
            if (lane == 0) out[b] = (m + lg2(s)) * LN2;
        }
    }
}

// ---------------------------------------------------------------------------
extern "C" void kernel_launch(void* const* d_in, const int* in_sizes, int n_in,
                              void* d_out, int out_size) {
    const int*   inputs     = (const int*)  d_in[0];
    const float* input_logp = (const float*)d_in[1];
    const int*   prod_ids   = (const int*)  d_in[2];  // (L, E, 2)
    const int*   sum_ch_ids = (const int*)  d_in[3];  // (L, N, C)
    const float* sum_logw   = (const float*)d_in[4];  // (L, N, C)
    const float* root_logw  = (const float*)d_in[5];  // (N,)
    float* out = (float*)d_out;

    circuit_kernel<<<GRID_BLOCKS, THREADS>>>(
        inputs, input_logp,
        reinterpret_cast<const int2*>(prod_ids),
        sum_ch_ids,
        reinterpret_cast<const float4*>(sum_logw),
        root_logw, out);
}

// round 10
// speedup vs baseline: 1.4527x; 1.0966x over previous
#include <cuda_runtime.h>
#include <math_constants.h>

// Problem constants
#define NUM_VARS 64
#define KK       32
#define NUM_CATS 256
#define NUM_INPUT (NUM_VARS * KK)   // 2048
#define LL       4
#define EE       16384
#define NN       8192
#define CC       4
#define BB       1024
#define Q4       (BB / 4)           // 256 ushort4-groups per row
#define TOTAL_NODES (NUM_INPUT + LL * NN)  // 34816
#define NCHUNK   64
#define MAX_NPB  14                 // max nodes per block per layer

#define GRID_BLOCKS 592             // 4 blocks/SM on 148 SMs — co-resident
#define THREADS     256
#define NTHREADS    (GRID_BLOCKS * THREADS)

#define LOG2E 1.4426950408889634f
#define LN2   0.6931471805599453f
#define QSCALE   128.0f             // u16 = -v_log2 * 128, clamp 32767
#define INVQ     (1.0f / 128.0f)
#define MAGIC    8388608.0f         // 2^23
#define MAGIC_HI 0x4B000000u

// Node pool quantized to u16 (71.3 MB — fully L2-resident)
__device__ unsigned short g_node_q[(size_t)TOTAL_NODES * BB];
__device__ float g_partial[NCHUNK * BB];
__device__ uint2 g_pairs[LL * NN * CC];   // pre-scaled row offsets (row * Q4)

// Grid barrier
__device__ unsigned g_bar_count;
__device__ volatile unsigned g_bar_gen;

__device__ __forceinline__ void grid_sync() {
    __syncthreads();
    if (threadIdx.x == 0) {
        __threadfence();
        unsigned gen = g_bar_gen;
        if (atomicAdd(&g_bar_count, 1u) == GRID_BLOCKS - 1u) {
            g_bar_count = 0;
            __threadfence();
            g_bar_gen = gen + 1u;
        } else {
            while (g_bar_gen == gen) { }
        }
    }
    __syncthreads();
    __threadfence();
}

__device__ __forceinline__ float ex2(float x) {
    float r; asm("ex2.approx.ftz.f32 %0, %1;" : "=f"(r) : "f"(x)); return r;
}
__device__ __forceinline__ float lg2(float x) {
    float r; asm("lg2.approx.ftz.f32 %0, %1;" : "=f"(r) : "f"(x)); return r;
}

__device__ __forceinline__ float lse4_2(float a, float b, float c, float d) {
    float m = fmaxf(fmaxf(a, b), fmaxf(c, d));
    float s = ex2(a - m) + ex2(b - m) + ex2(c - m) + ex2(d - m);
    return m + lg2(s);
}

__device__ __forceinline__ float dec_lo(unsigned s, float wq) {
    const float f = __uint_as_float(__byte_perm(s, MAGIC_HI, 0x7610));
    return fmaf(f, -INVQ, wq);
}
__device__ __forceinline__ float dec_hi(unsigned s, float wq) {
    const float f = __uint_as_float(__byte_perm(s, MAGIC_HI, 0x7632));
    return fmaf(f, -INVQ, wq);
}
__device__ __forceinline__ unsigned enc1(float v_log2) {
    unsigned q = __float2uint_rn(-v_log2 * QSCALE);
    return umin(q, 32767u);
}

// ---- software-pipeline stages ---------------------------------------------
struct Data { uint2 a0, q0, a1, q1, a2, q2, a3, q3; };

__device__ __forceinline__ void gather(Data& d, const unsigned* s_pairs, int i,
                                       const uint2* __restrict__ nq, unsigned c4) {
    const uint4 pa = *reinterpret_cast<const uint4*>(s_pairs + i * 8);
    const uint4 pb = *reinterpret_cast<const uint4*>(s_pairs + i * 8 + 4);
    d.a0 = __ldg(nq + pa.x + c4);
    d.q0 = __ldg(nq + pa.y + c4);
    d.a1 = __ldg(nq + pa.z + c4);
    d.q1 = __ldg(nq + pa.w + c4);
    d.a2 = __ldg(nq + pb.x + c4);
    d.q2 = __ldg(nq + pb.y + c4);
    d.a3 = __ldg(nq + pb.z + c4);
    d.q3 = __ldg(nq + pb.w + c4);
}

__device__ __forceinline__ void compute_store(const Data& d, const float4* s_w, int i,
                                              uint2* __restrict__ nqo,
                                              unsigned row, unsigned c4) {
    const float4 w = s_w[i];
    const float wq0 = fmaf(w.x, LOG2E, MAGIC * INVQ);
    const float wq1 = fmaf(w.y, LOG2E, MAGIC * INVQ);
    const float wq2 = fmaf(w.z, LOG2E, MAGIC * INVQ);
    const float wq3 = fmaf(w.w, LOG2E, MAGIC * INVQ);

    const unsigned s0x = __vadd2(d.a0.x, d.q0.x), s0y = __vadd2(d.a0.y, d.q0.y);
    const unsigned s1x = __vadd2(d.a1.x, d.q1.x), s1y = __vadd2(d.a1.y, d.q1.y);
    const unsigned s2x = __vadd2(d.a2.x, d.q2.x), s2y = __vadd2(d.a2.y, d.q2.y);
    const unsigned s3x = __vadd2(d.a3.x, d.q3.x), s3y = __vadd2(d.a3.y, d.q3.y);

    const float o0 = lse4_2(dec_lo(s0x, wq0), dec_lo(s1x, wq1),
                            dec_lo(s2x, wq2), dec_lo(s3x, wq3));
    const float o1 = lse4_2(dec_hi(s0x, wq0), dec_hi(s1x, wq1),
                            dec_hi(s2x, wq2), dec_hi(s3x, wq3));
    const float o2 = lse4_2(dec_lo(s0y, wq0), dec_lo(s1y, wq1),
                            dec_lo(s2y, wq2), dec_lo(s3y, wq3));
    const float o3 = lse4_2(dec_hi(s0y, wq0), dec_hi(s1y, wq1),
                            dec_hi(s2y, wq2), dec_hi(s3y, wq3));

    uint2 qo;
    qo.x = __byte_perm(enc1(o0), enc1(o1), 0x5410);
    qo.y = __byte_perm(enc1(o2), enc1(o3), 0x5410);
    nqo[row * Q4 + c4] = qo;
}

__global__ void __launch_bounds__(THREADS, 4)
circuit_kernel(const int* __restrict__ inputs,
               const float* __restrict__ input_logp,
               const int2* __restrict__ prod_ids,     // (L, E)
               const int* __restrict__ sum_ch_ids,    // (L, N, C)
               const float4* __restrict__ sum_logw,   // (L, N) as float4
               const float* __restrict__ root_logw,   // (N,)
               float* __restrict__ out) {
    const int gtid = blockIdx.x * THREADS + threadIdx.x;

    __shared__ unsigned s_pairs[MAX_NPB * 8];
    __shared__ float4   s_w[MAX_NPB];

    // ---------- Phase 0: input quantize + resolve ------------------------------
    for (int idx = gtid; idx < NUM_INPUT * BB; idx += NTHREADS) {
        const int v = idx >> 15;
        const int k = (idx >> 10) & (KK - 1);
        const int b = idx & (BB - 1);
        const int cat = __ldg(inputs + b * NUM_VARS + v);
        const float lp2 = __ldg(input_logp + ((v * KK + k) << 8) + cat) * LOG2E;
        g_node_q[idx] = (unsigned short)enc1(lp2);
    }
    for (int idx = gtid; idx < LL * NN * CC; idx += NTHREADS) {
        const int l = idx / (NN * CC);
        const int e = __ldg(sum_ch_ids + idx);
        const int2 p = __ldg(prod_ids + (size_t)l * EE + e);
        g_pairs[idx] = make_uint2((unsigned)p.x * Q4, (unsigned)p.y * Q4);
    }
    grid_sync();

    // ---------- Phases 1..4: sum layers — smem-staged idx + 2-stage pipeline ---
    const uint2* nq = reinterpret_cast<const uint2*>(g_node_q);
    uint2* nqo = reinterpret_cast<uint2*>(g_node_q);
    const unsigned c4 = threadIdx.x;   // ushort4-column 0..255

    // contiguous node chunk for this block
    const int start = (int)(((long long)blockIdx.x * NN) / GRID_BLOCKS);
    const int end   = (int)(((long long)(blockIdx.x + 1) * NN) / GRID_BLOCKS);
    const int cnt   = end - start;     // 13 or 14

    for (int l = 0; l < LL; l++) {
        const unsigned out_row0 = (unsigned)(NUM_INPUT + l * NN + start);
        const unsigned* gp = reinterpret_cast<const unsigned*>(g_pairs + (size_t)l * NN * CC);
        const float* gw = reinterpret_cast<const float*>(sum_logw + (size_t)l * NN);

        // stage this block's indices + weights into smem (coalesced)
        for (int t = threadIdx.x; t < cnt * 8; t += THREADS)
            s_pairs[t] = gp[start * 8 + t];
        for (int t = threadIdx.x; t < cnt * 4; t += THREADS)
            reinterpret_cast<float*>(s_w)[t] = gw[start * 4 + t];
        __syncthreads();

        // 2-stage pipeline, unrolled x2 (no register-copy MOVs)
        Data dA, dB;
        int i = 0;
        gather(dA, s_pairs, 0, nq, c4);
        while (i + 2 <= cnt) {
            gather(dB, s_pairs, i + 1, nq, c4);
            compute_store(dA, s_w, i, nqo, out_row0 + i, c4);
            if (i + 2 < cnt)
                gather(dA, s_pairs, i + 2, nq, c4);
            compute_store(dB, s_w, i + 1, nqo, out_row0 + i + 1, c4);
            i += 2;
        }
        if (i < cnt)
            compute_store(dA, s_w, i, nqo, out_row0 + i, c4);

        grid_sync();   // leading __syncthreads also protects smem reuse next layer
    }

    // ---------- Phase 5: root partial logsumexp (decode u16, float) -----------
    {
        const unsigned short* last = g_node_q + (size_t)(NUM_INPUT + (LL - 1) * NN) * BB;
        const int idx = gtid;
        if (idx < NCHUNK * BB) {
            const int chunk = idx >> 10;
            const int b = idx & (BB - 1);
            const int n0 = chunk * (NN / NCHUNK);
            float m = -CUDART_INF_F, s = 0.f;
#pragma unroll 4
            for (int i2 = 0; i2 < NN / NCHUNK; i2++) {
                const int n = n0 + i2;
                const float nv = -(float)last[(unsigned)n * BB + b] * INVQ;
                const float x = fmaf(__ldg(root_logw + n), LOG2E, nv);
                const float mn = fmaxf(m, x);
                s = s * ex2(m - mn) + ex2(x - mn);
                m = mn;
            }
            g_partial[chunk * BB + b] = m + lg2(s);
        }
    }
    grid_sync();

    // ---------- Phase 6: final combine (-> natural log) -----------------------
    {
        const int wgid = gtid >> 5;
        const int lane = gtid & 31;
        if (wgid < BB) {
            const int b = wgid;
            const float x0 = g_partial[lane * BB + b];
            const float x1 = g_partial[(lane + 32) * BB + b];
            float m = fmaxf(x0, x1);
#pragma unroll
            for (int o = 16; o > 0; o >>= 1)
                m = fmaxf(m, __shfl_xor_sync(0xFFFFFFFF, m, o));
            float s = ex2(x0 - m) + ex2(x1 - m);
#pragma unroll
            for (int o = 16; o > 0; o >>= 1)
                s += __shfl_xor_sync(0xFFFFFFFF, s, o);
            if (lane == 0) out[b] = (m + lg2(s)) * LN2;
        }
    }
}

// ---------------------------------------------------------------------------
extern "C" void kernel_launch(void* const* d_in, const int* in_sizes, int n_in,
                              void* d_out, int out_size) {
    const int*   inputs     = (const int*)  d_in[0];
    const float* input_logp = (const float*)d_in[1];
    const int*   prod_ids   = (const int*)  d_in[2];  // (L, E, 2)
    const int*   sum_ch_ids = (const int*)  d_in[3];  // (L, N, C)
    const float* sum_logw   = (const float*)d_in[4];  // (L, N, C)
    const float* root_logw  = (const float*)d_in[5];  // (N,)
    float* out = (float*)d_out;

    circuit_kernel<<<GRID_BLOCKS, THREADS>>>(
        inputs, input_logp,
        reinterpret_cast<const int2*>(prod_ids),
        sum_ch_ids,
        reinterpret_cast<const float4*>(sum_logw),
        root_logw, out);
}

// round 11
// speedup vs baseline: 1.4640x; 1.0078x over previous
#include <cuda_runtime.h>
#include <math_constants.h>

// Problem constants
#define NUM_VARS 64
#define KK       32
#define NUM_CATS 256
#define NUM_INPUT (NUM_VARS * KK)   // 2048
#define LL       4
#define EE       16384
#define NN       8192
#define CC       4
#define BB       1024
#define Q4       (BB / 4)           // 256 ushort4-groups per row
#define TOTAL_NODES (NUM_INPUT + LL * NN)  // 34816
#define NCHUNK   64
#define MAX_NPB  14                 // max nodes per block per layer

#define GRID_BLOCKS 592             // 4 blocks/SM on 148 SMs — co-resident
#define THREADS     256
#define NTHREADS    (GRID_BLOCKS * THREADS)

#define LOG2E 1.4426950408889634f
#define LN2   0.6931471805599453f
#define QSCALE   128.0f             // u16 = -v_log2 * 128, clamp 32767
#define INVQ     (1.0f / 128.0f)
#define MAGIC    8388608.0f         // 2^23
#define MAGIC_HI 0x4B000000u

// Node pool quantized to u16 (71.3 MB — fully L2-resident)
__device__ unsigned short g_node_q[(size_t)TOTAL_NODES * BB];
__device__ float g_partial[NCHUNK * BB];
__device__ uint2 g_pairs[LL * NN * CC];   // pre-scaled row offsets (row * Q4)

// Grid barrier
__device__ unsigned g_bar_count;
__device__ volatile unsigned g_bar_gen;

__device__ __forceinline__ void grid_sync() {
    __syncthreads();
    if (threadIdx.x == 0) {
        __threadfence();
        unsigned gen = g_bar_gen;
        if (atomicAdd(&g_bar_count, 1u) == GRID_BLOCKS - 1u) {
            g_bar_count = 0;
            __threadfence();
            g_bar_gen = gen + 1u;
        } else {
            while (g_bar_gen == gen) { }
        }
    }
    __syncthreads();
    __threadfence();
}

__device__ __forceinline__ float ex2(float x) {
    float r; asm("ex2.approx.ftz.f32 %0, %1;" : "=f"(r) : "f"(x)); return r;
}
__device__ __forceinline__ float lg2(float x) {
    float r; asm("lg2.approx.ftz.f32 %0, %1;" : "=f"(r) : "f"(x)); return r;
}

// f16x2 helpers: pack two f32 (lo, hi), half2 ex2 (one MUFU op = 2 values), half2 add
__device__ __forceinline__ unsigned pk16(float lo, float hi) {
    unsigned h;
    asm("cvt.rn.f16x2.f32 %0, %1, %2;" : "=r"(h) : "f"(hi), "f"(lo));
    return h;
}
__device__ __forceinline__ unsigned ex2h2(unsigned h) {
    unsigned r;
    asm("ex2.approx.f16x2 %0, %1;" : "=r"(r) : "r"(h));
    return r;
}
__device__ __forceinline__ unsigned haddh2(unsigned a, unsigned b) {
    unsigned r;
    asm("add.rn.f16x2 %0, %1, %2;" : "=r"(r) : "r"(a), "r"(b));
    return r;
}
__device__ __forceinline__ void unpk(unsigned s, float& lo, float& hi) {
    asm("{\n\t.reg .b16 l, h;\n\tmov.b32 {l, h}, %2;\n\t"
        "cvt.f32.f16 %0, l;\n\tcvt.f32.f16 %1, h;\n\t}"
        : "=f"(lo), "=f"(hi) : "r"(s));
}

__device__ __forceinline__ float dec_lo(unsigned s, float wq) {
    const float f = __uint_as_float(__byte_perm(s, MAGIC_HI, 0x7610));
    return fmaf(f, -INVQ, wq);
}
__device__ __forceinline__ float dec_hi(unsigned s, float wq) {
    const float f = __uint_as_float(__byte_perm(s, MAGIC_HI, 0x7632));
    return fmaf(f, -INVQ, wq);
}
__device__ __forceinline__ unsigned enc1(float v_log2) {
    unsigned q = __float2uint_rn(-v_log2 * QSCALE);
    return umin(q, 32767u);
}

// ---- software-pipeline stages ---------------------------------------------
struct Data { uint2 a0, q0, a1, q1, a2, q2, a3, q3; };

__device__ __forceinline__ void gather(Data& d, const unsigned* s_pairs, int i,
                                       const uint2* __restrict__ nq, unsigned c4) {
    const uint4 pa = *reinterpret_cast<const uint4*>(s_pairs + i * 8);
    const uint4 pb = *reinterpret_cast<const uint4*>(s_pairs + i * 8 + 4);
    d.a0 = __ldg(nq + pa.x + c4);
    d.q0 = __ldg(nq + pa.y + c4);
    d.a1 = __ldg(nq + pa.z + c4);
    d.q1 = __ldg(nq + pa.w + c4);
    d.a2 = __ldg(nq + pb.x + c4);
    d.q2 = __ldg(nq + pb.y + c4);
    d.a3 = __ldg(nq + pb.z + c4);
    d.q3 = __ldg(nq + pb.w + c4);
}

__device__ __forceinline__ void compute_store(const Data& d, const float4* s_w, int i,
                                              uint2* __restrict__ nqo,
                                              unsigned row, unsigned c4) {
    const float4 w = s_w[i];
    const float wq0 = fmaf(w.x, LOG2E, MAGIC * INVQ);
    const float wq1 = fmaf(w.y, LOG2E, MAGIC * INVQ);
    const float wq2 = fmaf(w.z, LOG2E, MAGIC * INVQ);
    const float wq3 = fmaf(w.w, LOG2E, MAGIC * INVQ);

    const unsigned s0x = __vadd2(d.a0.x, d.q0.x), s0y = __vadd2(d.a0.y, d.q0.y);
    const unsigned s1x = __vadd2(d.a1.x, d.q1.x), s1y = __vadd2(d.a1.y, d.q1.y);
    const unsigned s2x = __vadd2(d.a2.x, d.q2.x), s2y = __vadd2(d.a2.y, d.q2.y);
    const unsigned s3x = __vadd2(d.a3.x, d.q3.x), s3y = __vadd2(d.a3.y, d.q3.y);

    // x[child][col]
    const float x00 = dec_lo(s0x, wq0), x01 = dec_hi(s0x, wq0);
    const float x02 = dec_lo(s0y, wq0), x03 = dec_hi(s0y, wq0);
    const float x10 = dec_lo(s1x, wq1), x11 = dec_hi(s1x, wq1);
    const float x12 = dec_lo(s1y, wq1), x13 = dec_hi(s1y, wq1);
    const float x20 = dec_lo(s2x, wq2), x21 = dec_hi(s2x, wq2);
    const float x22 = dec_lo(s2y, wq2), x23 = dec_hi(s2y, wq2);
    const float x30 = dec_lo(s3x, wq3), x31 = dec_hi(s3x, wq3);
    const float x32 = dec_lo(s3y, wq3), x33 = dec_hi(s3y, wq3);

    // per-column max over children
    const float m0 = fmaxf(fmaxf(x00, x10), fmaxf(x20, x30));
    const float m1 = fmaxf(fmaxf(x01, x11), fmaxf(x21, x31));
    const float m2 = fmaxf(fmaxf(x02, x12), fmaxf(x22, x32));
    const float m3 = fmaxf(fmaxf(x03, x13), fmaxf(x23, x33));

    // half2 ex2: one MUFU op per 2 columns per child (8 instead of 16)
    const unsigned r0A = ex2h2(pk16(x00 - m0, x01 - m1));
    const unsigned r1A = ex2h2(pk16(x10 - m0, x11 - m1));
    const unsigned r2A = ex2h2(pk16(x20 - m0, x21 - m1));
    const unsigned r3A = ex2h2(pk16(x30 - m0, x31 - m1));
    const unsigned r0B = ex2h2(pk16(x02 - m2, x03 - m3));
    const unsigned r1B = ex2h2(pk16(x12 - m2, x13 - m3));
    const unsigned r2B = ex2h2(pk16(x22 - m2, x23 - m3));
    const unsigned r3B = ex2h2(pk16(x32 - m2, x33 - m3));

    const unsigned sA = haddh2(haddh2(r0A, r1A), haddh2(r2A, r3A));
    const unsigned sB = haddh2(haddh2(r0B, r1B), haddh2(r2B, r3B));

    float sf0, sf1, sf2, sf3;
    unpk(sA, sf0, sf1);
    unpk(sB, sf2, sf3);

    const float o0 = m0 + lg2(sf0);
    const float o1 = m1 + lg2(sf1);
    const float o2 = m2 + lg2(sf2);
    const float o3 = m3 + lg2(sf3);

    uint2 qo;
    qo.x = __byte_perm(enc1(o0), enc1(o1), 0x5410);
    qo.y = __byte_perm(enc1(o2), enc1(o3), 0x5410);
    nqo[row * Q4 + c4] = qo;
}

__global__ void __launch_bounds__(THREADS, 4)
circuit_kernel(const int* __restrict__ inputs,
               const float* __restrict__ input_logp,
               const int2* __restrict__ prod_ids,     // (L, E)
               const int* __restrict__ sum_ch_ids,    // (L, N, C)
               const float4* __restrict__ sum_logw,   // (L, N) as float4
               const float* __restrict__ root_logw,   // (N,)
               float* __restrict__ out) {
    const int gtid = blockIdx.x * THREADS + threadIdx.x;

    __shared__ unsigned s_pairs[MAX_NPB * 8];
    __shared__ float4   s_w[MAX_NPB];

    // ---------- Phase 0: input quantize + resolve ------------------------------
    for (int idx = gtid; idx < NUM_INPUT * BB; idx += NTHREADS) {
        const int v = idx >> 15;
        const int k = (idx >> 10) & (KK - 1);
        const int b = idx & (BB - 1);
        const int cat = __ldg(inputs + b * NUM_VARS + v);
        const float lp2 = __ldg(input_logp + ((v * KK + k) << 8) + cat) * LOG2E;
        g_node_q[idx] = (unsigned short)enc1(lp2);
    }
    for (int idx = gtid; idx < LL * NN * CC; idx += NTHREADS) {
        const int l = idx / (NN * CC);
        const int e = __ldg(sum_ch_ids + idx);
        const int2 p = __ldg(prod_ids + (size_t)l * EE + e);
        g_pairs[idx] = make_uint2((unsigned)p.x * Q4, (unsigned)p.y * Q4);
    }
    grid_sync();

    // ---------- Phases 1..4: sum layers — smem-staged idx + 2-stage pipeline ---
    const uint2* nq = reinterpret_cast<const uint2*>(g_node_q);
    uint2* nqo = reinterpret_cast<uint2*>(g_node_q);
    const unsigned c4 = threadIdx.x;   // ushort4-column 0..255

    const int start = (int)(((long long)blockIdx.x * NN) / GRID_BLOCKS);
    const int end   = (int)(((long long)(blockIdx.x + 1) * NN) / GRID_BLOCKS);
    const int cnt   = end - start;     // 13 or 14

    for (int l = 0; l < LL; l++) {
        const unsigned out_row0 = (unsigned)(NUM_INPUT + l * NN + start);
        const unsigned* gp = reinterpret_cast<const unsigned*>(g_pairs + (size_t)l * NN * CC);
        const float* gw = reinterpret_cast<const float*>(sum_logw + (size_t)l * NN);

        for (int t = threadIdx.x; t < cnt * 8; t += THREADS)
            s_pairs[t] = gp[start * 8 + t];
        for (int t = threadIdx.x; t < cnt * 4; t += THREADS)
            reinterpret_cast<float*>(s_w)[t] = gw[start * 4 + t];
        __syncthreads();

        Data dA, dB;
        int i = 0;
        gather(dA, s_pairs, 0, nq, c4);
        while (i + 2 <= cnt) {
            gather(dB, s_pairs, i + 1, nq, c4);
            compute_store(dA, s_w, i, nqo, out_row0 + i, c4);
            if (i + 2 < cnt)
                gather(dA, s_pairs, i + 2, nq, c4);
            compute_store(dB, s_w, i + 1, nqo, out_row0 + i + 1, c4);
            i += 2;
        }
        if (i < cnt)
            compute_store(dA, s_w, i, nqo, out_row0 + i, c4);

        grid_sync();
    }

    // ---------- Phase 5: root partial logsumexp (decode u16, float) -----------
    {
        const unsigned short* last = g_node_q + (size_t)(NUM_INPUT + (LL - 1) * NN) * BB;
        const int idx = gtid;
        if (idx < NCHUNK * BB) {
            const int chunk = idx >> 10;
            const int b = idx & (BB - 1);
            const int n0 = chunk * (NN / NCHUNK);
            float m = -CUDART_INF_F, s = 0.f;
#pragma unroll 4
            for (int i2 = 0; i2 < NN / NCHUNK; i2++) {
                const int n = n0 + i2;
                const float nv = -(float)last[(unsigned)n * BB + b] * INVQ;
                const float x = fmaf(__ldg(root_logw + n), LOG2E, nv);
                const float mn = fmaxf(m, x);
                s = s * ex2(m - mn) + ex2(x - mn);
                m = mn;
            }
            g_partial[chunk * BB + b] = m + lg2(s);
        }
    }
    grid_sync();

    // ---------- Phase 6: final combine (-> natural log) -----------------------
    {
        const int wgid = gtid >> 5;
        const int lane = gtid & 31;
        if (wgid < BB) {
            const int b = wgid;
            const float x0 = g_partial[lane * BB + b];
            const float x1 = g_partial[(lane + 32) * BB + b];
            float m = fmaxf(x0, x1);
#pragma unroll
            for (int o = 16; o > 0; o >>= 1)
                m = fmaxf(m, __shfl_xor_sync(0xFFFFFFFF, m, o));
            float s = ex2(x0 - m) + ex2(x1 - m);
#pragma unroll
            for (int o = 16; o > 0; o >>= 1)
                s += __shfl_xor_sync(0xFFFFFFFF, s, o);
            if (lane == 0) out[b] = (m + lg2(s)) * LN2;
        }
    }
}

// ---------------------------------------------------------------------------
extern "C" void kernel_launch(void* const* d_in, const int* in_sizes, int n_in,
                              void* d_out, int out_size) {
    const int*   inputs     = (const int*)  d_in[0];
    const float* input_logp = (const float*)d_in[1];
    const int*   prod_ids   = (const int*)  d_in[2];  // (L, E, 2)
    const int*   sum_ch_ids = (const int*)  d_in[3];  // (L, N, C)
    const float* sum_logw   = (const float*)d_in[4];  // (L, N, C)
    const float* root_logw  = (const float*)d_in[5];  // (N,)
    float* out = (float*)d_out;

    circuit_kernel<<<GRID_BLOCKS, THREADS>>>(
        inputs, input_logp,
        reinterpret_cast<const int2*>(prod_ids),
        sum_ch_ids,
        reinterpret_cast<const float4*>(sum_logw),
        root_logw, out);
}